// round 9
// baseline (speedup 1.0000x reference)
#include <cuda_runtime.h>
#include <cuda_fp16.h>
#include <stdint.h>

// CosRec fused kernel — fp16 mma.sync (HMMA), round 9.
// vs round 8: all mainloop shared loads vectorized —
//  * A/B half2 tables re-laid out so (k2, k2+4) pairs are adjacent -> LDS.64
//    (stride 56 words: conflict-free per half-warp phase),
//  * Wf2 b-fragments pair-packed (n-tile pairs interleaved) -> LDS.128.
// Per ks-step: 10 LDS instead of 19 (same bytes, 2x MLP per instruction).

#define THREADS 256
#define TSTR 56            // table row stride in words (paired layout)

// ---- shared memory byte offsets ----
#define OFF_SI    0        // 36 ints
#define OFF_SX    160      // 164 floats (ends 816)
#define OFF_A2    1024     // uint32 A-table [32 c][56] = 7168 B
#define OFF_B2    8192     // uint32 B-table [32 a][56] = 7168 B
#define OFF_X     15360    // region X: W1 staging 25600 B, then bfrag arrays
#define OFF_F12   36864    // (OFF_X + 21504) bfrag12: 7*32*8 = 1792 B
#define OFF_AF    40960    // fp32 A [100 f][32 c] = 12800 B
#define OFF_BF    53760    // fp32 B [100 f][32 a] = 12800 B
#define OFF_ET    66560    // fp32 E^T [64][33] = 8448 B ; later sRedW[8][104]
#define SMEM_TOTAL 75008

__device__ __forceinline__ void mma16816(float* d, uint32_t a0, uint32_t a1,
                                         uint32_t a2, uint32_t a3,
                                         uint32_t b0, uint32_t b1) {
    asm volatile(
        "mma.sync.aligned.m16n8k16.row.col.f32.f16.f16.f32 "
        "{%0,%1,%2,%3}, {%4,%5,%6,%7}, {%8,%9}, {%0,%1,%2,%3};"
        : "+f"(d[0]), "+f"(d[1]), "+f"(d[2]), "+f"(d[3])
        : "r"(a0), "r"(a1), "r"(a2), "r"(a3), "r"(b0), "r"(b1));
}

__device__ __forceinline__ uint32_t hbuild(uint32_t a, uint32_t b) {
    __half2 av = *reinterpret_cast<__half2*>(&a);
    __half2 bv = *reinterpret_cast<__half2*>(&b);
    __half2 r  = __hmax2(__hadd2(av, bv), __float2half2_rn(0.0f));
    return *reinterpret_cast<uint32_t*>(&r);
}

// paired slot: (k2, k2+4) adjacent -> slot = blk + tig*2 + hi
__device__ __forceinline__ int pslot(int kk) {
    return (kk & ~7) + ((kk & 3) << 1) + ((kk >> 2) & 1);
}

__global__ __launch_bounds__(THREADS, 2)
void cosrec_kernel(
    const int*   __restrict__ seq_var,   // [512*32]
    const int*   __restrict__ user_var,  // [512]
    const int*   __restrict__ item_var,  // [512*3]
    const float* __restrict__ item_emb,  // [100000*64]
    const float* __restrict__ user_emb,  // [100000*64]
    const float* __restrict__ W2,        // [100000*164]
    const float* __restrict__ b2,        // [100000]
    const float* __restrict__ W1,        // [100*128]
    const float* __restrict__ b1,        // [100]
    const float* __restrict__ Wf2,       // [100*100]
    const float* __restrict__ bf2,       // [100]
    float*       __restrict__ out)       // [512*3]
{
    extern __shared__ char smem[];
    int*      sI  = (int*)(smem + OFF_SI);
    float*    sX  = (float*)(smem + OFF_SX);
    uint32_t* uA2 = (uint32_t*)(smem + OFF_A2);
    uint32_t* uB2 = (uint32_t*)(smem + OFF_B2);
    float*    sAf = (float*)(smem + OFF_AF);
    float*    sBf = (float*)(smem + OFF_BF);
    float*    sEt = (float*)(smem + OFF_ET);

    const int b    = blockIdx.x;
    const int tid  = threadIdx.x;
    const int wid  = tid >> 5;
    const int lane = tid & 31;

    // ---- phase 0: indices ----
    if (tid < 32)       sI[tid] = seq_var[b * 32 + tid];
    else if (tid < 35)  sI[tid] = item_var[b * 3 + (tid - 32)];
    else if (tid == 35) sI[35]  = user_var[b];
    __syncthreads();

    // ---- phase 1: gather E^T ----
    for (int idx = tid; idx < 2048; idx += THREADS) {
        int l = idx >> 6, d = idx & 63;
        sEt[d * 33 + l] = item_emb[(size_t)sI[l] * 64 + d];
    }

    // ---- phase 2: A = E@Wa^T + b1, B = E@Wb^T (W1 staged in region X) ----
    float* sW1c = (float*)(smem + OFF_X);  // [100][64]
    for (int c = 0; c < 2; ++c) {
        __syncthreads();
        for (int idx = tid; idx < 6400; idx += THREADS) {
            int f = idx >> 6, jj = idx & 63;
            int half_ = jj >> 5, j = jj & 31;
            sW1c[idx] = W1[f * 128 + half_ * 64 + c * 32 + j];
        }
        __syncthreads();
        for (int idx = tid; idx < 3200; idx += THREADS) {
            int f = idx >> 5, l = idx & 31;
            float accA = 0.0f, accB = 0.0f;
            #pragma unroll
            for (int j = 0; j < 32; ++j) {
                float e = sEt[(c * 32 + j) * 33 + l];
                accA = fmaf(e, sW1c[f * 64 + j],      accA);
                accB = fmaf(e, sW1c[f * 64 + 32 + j], accB);
            }
            if (c == 0) { sAf[idx] = accA;          sBf[idx] = accB; }
            else        { sAf[idx] += accA + b1[f]; sBf[idx] += accB; }
        }
    }
    __syncthreads();

    // ---- phase 3a: pack half2 tables, transposed + pair-slotted, stride 56 ----
    // k2 < 50: real (k=2*k2, 2*k2+1). k2 == 50: bias col (A=(1,0), B=(0,0)).
    // k2 in (50,56): zero padding.
    for (int idx = tid; idx < 32 * 56; idx += THREADS) {
        int c = idx / 56, kk = idx - c * 56;
        __half2 va, vb;
        if (kk < 50) {
            va = __floats2half2_rn(sAf[(2 * kk) * 32 + c], sAf[(2 * kk + 1) * 32 + c]);
            vb = __floats2half2_rn(sBf[(2 * kk) * 32 + c], sBf[(2 * kk + 1) * 32 + c]);
        } else if (kk == 50) {
            va = __floats2half2_rn(1.0f, 0.0f);
            vb = __float2half2_rn(0.0f);
        } else {
            va = __float2half2_rn(0.0f);
            vb = __float2half2_rn(0.0f);
        }
        int s = pslot(kk);
        uA2[c * TSTR + s] = *reinterpret_cast<uint32_t*>(&va);
        uB2[c * TSTR + s] = *reinterpret_cast<uint32_t*>(&vb);
    }
    __syncthreads();   // W1 staging dead; bfrag arrays overlay region X

    // ---- phase 3b: pack Wf2 B-fragments, n-tile PAIRS interleaved ----
    // W(n,k): n<100 & k<100 -> Wf2[n][k]; n<100 & k==100 -> bf2[n]; else 0.
    // nt<12 -> uint4 array bfragP[(nt/2 *7 + ks)*32 + ln], half (nt&1).
    // nt==12 -> uint2 array bfrag12[ks*32 + ln].
    for (int idx = tid; idx < 13 * 7 * 32; idx += THREADS) {
        int nt  = idx / 224;
        int rem = idx - nt * 224;
        int ks  = rem >> 5, ln = rem & 31;
        int n   = nt * 8 + (ln >> 2);
        int k0  = ks * 16 + (ln & 3) * 2;
        float w0, w1, w2v, w3v;
        if (n < 100) {
            const float* wr = Wf2 + n * 100;
            w0  = (k0     < 100) ? wr[k0]     : ((k0     == 100) ? bf2[n] : 0.0f);
            w1  = (k0 + 1 < 100) ? wr[k0 + 1] : ((k0 + 1 == 100) ? bf2[n] : 0.0f);
            w2v = (k0 + 8 < 100) ? wr[k0 + 8] : ((k0 + 8 == 100) ? bf2[n] : 0.0f);
            w3v = (k0 + 9 < 100) ? wr[k0 + 9] : ((k0 + 9 == 100) ? bf2[n] : 0.0f);
        } else {
            w0 = w1 = w2v = w3v = 0.0f;
        }
        __half2 lo = __floats2half2_rn(w0, w1);
        __half2 hi = __floats2half2_rn(w2v, w3v);
        uint2 val;
        val.x = *reinterpret_cast<uint32_t*>(&lo);
        val.y = *reinterpret_cast<uint32_t*>(&hi);
        if (nt < 12) {
            *(uint2*)(smem + OFF_X + (((nt >> 1) * 7 + ks) * 32 + ln) * 16
                               + (nt & 1) * 8) = val;
        } else {
            *(uint2*)(smem + OFF_F12 + (ks * 32 + ln) * 8) = val;
        }
    }
    __syncthreads();

    // ---- mainloop: 8 m-tiles of 16 pairs per warp; no CTA syncs ----
    const int gid = lane >> 2;   // row group 0..7
    const int tig = lane & 3;    // k group 0..3
    const uint4* bfragP  = (const uint4*)(smem + OFF_X);
    const uint2* bfrag12 = (const uint2*)(smem + OFF_F12);

    float xacc[26];
    #pragma unroll
    for (int j = 0; j < 26; ++j) xacc[j] = 0.0f;

    for (int mt = 0; mt < 8; ++mt) {
        // pair p0 = wid*128 + mt*16 + gid, p1 = p0 + 8; aI warp-uniform.
        const int p0 = wid * 128 + mt * 16 + gid;
        const int aI = p0 >> 5;
        const int cA = p0 & 31;
        const int cB = cA + 8;

        float acc[13][4];
        #pragma unroll
        for (int nt = 0; nt < 13; ++nt)
            #pragma unroll
            for (int e = 0; e < 4; ++e) acc[nt][e] = 0.0f;

        #pragma unroll
        for (int ks = 0; ks < 7; ++ks) {
            const int so = ks * 8 + tig * 2;     // paired slot offset
            uint2 Bab = *(const uint2*)&uB2[aI * TSTR + so];
            uint2 Aa  = *(const uint2*)&uA2[cA * TSTR + so];
            uint2 Ab  = *(const uint2*)&uA2[cB * TSTR + so];
            uint32_t a0 = hbuild(Aa.x, Bab.x);
            uint32_t a1 = hbuild(Ab.x, Bab.x);
            uint32_t a2 = hbuild(Aa.y, Bab.y);
            uint32_t a3 = hbuild(Ab.y, Bab.y);
            #pragma unroll
            for (int ntp = 0; ntp < 6; ++ntp) {
                uint4 bb = bfragP[(ntp * 7 + ks) * 32 + lane];
                mma16816(acc[ntp * 2],     a0, a1, a2, a3, bb.x, bb.y);
                mma16816(acc[ntp * 2 + 1], a0, a1, a2, a3, bb.z, bb.w);
            }
            uint2 b12 = bfrag12[ks * 32 + lane];
            mma16816(acc[12], a0, a1, a2, a3, b12.x, b12.y);
        }
        // relu + colsum into registers (rows p0 and p1)
        #pragma unroll
        for (int nt = 0; nt < 13; ++nt) {
            xacc[nt * 2]     += fmaxf(acc[nt][0], 0.0f) + fmaxf(acc[nt][2], 0.0f);
            xacc[nt * 2 + 1] += fmaxf(acc[nt][1], 0.0f) + fmaxf(acc[nt][3], 0.0f);
        }
    }

    // ---- reduction: shfl over row/k groups, then fixed-order over warps ----
    #pragma unroll
    for (int j = 0; j < 26; ++j) {
        float s = xacc[j];
        s += __shfl_down_sync(0xffffffffu, s, 16);
        s += __shfl_down_sync(0xffffffffu, s, 8);
        s += __shfl_down_sync(0xffffffffu, s, 4);
        xacc[j] = s;
    }
    float* sRedW = (float*)(smem + OFF_ET);  // [8][104], overlays dead E^T
    if (lane < 4) {
        #pragma unroll
        for (int nt = 0; nt < 13; ++nt) {
            int n0 = nt * 8 + lane * 2;      // lane == tig here
            sRedW[wid * 104 + n0]     = xacc[nt * 2];
            sRedW[wid * 104 + n0 + 1] = xacc[nt * 2 + 1];
        }
    }
    __syncthreads();
    if (tid < 100) {
        float s = 0.0f;
        #pragma unroll
        for (int w = 0; w < 8; ++w) s += sRedW[w * 104 + tid];
        sX[tid] = s;
    } else if (tid >= 128 && tid < 192) {
        int d = tid - 128;
        sX[100 + d] = user_emb[(size_t)sI[35] * 64 + d];
    }
    __syncthreads();

    // ---- out[b][t] = b2[item] + W2[item] . sX (one warp per t) ----
    if (wid < 3) {
        int it = sI[32 + wid];
        const float* w2p = W2 + (size_t)it * 164;
        float s = 0.0f;
        for (int j = lane; j < 164; j += 32) s = fmaf(w2p[j], sX[j], s);
        #pragma unroll
        for (int off = 16; off; off >>= 1)
            s += __shfl_down_sync(0xffffffffu, s, off);
        if (lane == 0) out[b * 3 + wid] = b2[it] + s;
    }
}

extern "C" void kernel_launch(void* const* d_in, const int* in_sizes, int n_in,
                              void* d_out, int out_size) {
    (void)in_sizes; (void)n_in; (void)out_size;
    cudaFuncSetAttribute(cosrec_kernel,
                         cudaFuncAttributeMaxDynamicSharedMemorySize, SMEM_TOTAL);
    cosrec_kernel<<<512, THREADS, SMEM_TOTAL>>>(
        (const int*)d_in[0],    // seq_var
        (const int*)d_in[1],    // user_var
        (const int*)d_in[2],    // item_var
        (const float*)d_in[3],  // item_emb
        (const float*)d_in[4],  // user_emb
        (const float*)d_in[5],  // W2
        (const float*)d_in[6],  // b2
        (const float*)d_in[7],  // W1
        (const float*)d_in[8],  // b1
        (const float*)d_in[9],  // Wf2
        (const float*)d_in[10], // bf2
        (float*)d_out);
}

// round 11
// speedup vs baseline: 1.0436x; 1.0436x over previous
#include <cuda_runtime.h>
#include <cuda_fp16.h>
#include <stdint.h>

// CosRec fused kernel — fp16 mma.sync (HMMA), round 11 (= round 10 fixed).
// TWO batch rows per CTA (grid 256 -> single wave at 2 CTAs/SM; Wf2
// b-fragments packed once, shared by both rows) + next-ks table prefetch.

#define THREADS 256
#define TSTR 56            // table row stride in words (paired layout)

// ---- shared memory byte offsets ----
#define OFF_SI     0       // 72 ints (two rows)                      288 B
#define OFF_SX     288     // 2 x 164 floats                         1312 B
#define OFF_BFRAGP 1664    // uint4 bfrag pairs: 6*7*32*16 =        21504 B
#define OFF_F12    23168   // uint2 bfrag nt=12: 7*32*8   =          1792 B
#define OFF_A2     24960   // uint32 A-table [32][56]     =          7168 B
#define OFF_B2     32128   // uint32 B-table [32][56]     =          7168 B
#define OFF_W1     39296   // W1 staging [100][64] f32    =         25600 B
#define OFF_AF     64896   // fp32 A [100][32]            =         12800 B
#define OFF_BF     77696   // fp32 B [100][32]            =         12800 B
#define OFF_ET     90496   // fp32 E^T [64][33] = 8448 B ; later sRedW[8][104]
#define SMEM_TOTAL 98944

__device__ __forceinline__ void mma16816(float* d, uint32_t a0, uint32_t a1,
                                         uint32_t a2, uint32_t a3,
                                         uint32_t b0, uint32_t b1) {
    asm volatile(
        "mma.sync.aligned.m16n8k16.row.col.f32.f16.f16.f32 "
        "{%0,%1,%2,%3}, {%4,%5,%6,%7}, {%8,%9}, {%0,%1,%2,%3};"
        : "+f"(d[0]), "+f"(d[1]), "+f"(d[2]), "+f"(d[3])
        : "r"(a0), "r"(a1), "r"(a2), "r"(a3), "r"(b0), "r"(b1));
}

__device__ __forceinline__ uint32_t hbuild(uint32_t a, uint32_t b) {
    __half2 av = *reinterpret_cast<__half2*>(&a);
    __half2 bv = *reinterpret_cast<__half2*>(&b);
    __half2 r  = __hmax2(__hadd2(av, bv), __float2half2_rn(0.0f));
    return *reinterpret_cast<uint32_t*>(&r);
}

// paired slot: (k2, k2+4) adjacent -> slot = blk + tig*2 + hi
__device__ __forceinline__ int pslot(int kk) {
    return (kk & ~7) + ((kk & 3) << 1) + ((kk >> 2) & 1);
}

__global__ __launch_bounds__(THREADS, 2)
void cosrec_kernel(
    const int*   __restrict__ seq_var,   // [512*32]
    const int*   __restrict__ user_var,  // [512]
    const int*   __restrict__ item_var,  // [512*3]
    const float* __restrict__ item_emb,  // [100000*64]
    const float* __restrict__ user_emb,  // [100000*64]
    const float* __restrict__ W2,        // [100000*164]
    const float* __restrict__ b2,        // [100000]
    const float* __restrict__ W1,        // [100*128]
    const float* __restrict__ b1,        // [100]
    const float* __restrict__ Wf2,       // [100*100]
    const float* __restrict__ bf2,       // [100]
    float*       __restrict__ out)       // [512*3]
{
    extern __shared__ char smem[];
    int*      sI  = (int*)(smem + OFF_SI);
    float*    sX  = (float*)(smem + OFF_SX);     // [2][164]
    uint32_t* uA2 = (uint32_t*)(smem + OFF_A2);
    uint32_t* uB2 = (uint32_t*)(smem + OFF_B2);
    float*    sAf = (float*)(smem + OFF_AF);
    float*    sBf = (float*)(smem + OFF_BF);
    float*    sEt = (float*)(smem + OFF_ET);

    const int row0 = blockIdx.x * 2;
    const int row1 = row0 + 1;
    const int tid  = threadIdx.x;
    const int wid  = tid >> 5;
    const int lane = tid & 31;

    // ---- phase 0: indices for both rows ----
    if (tid < 32)       sI[tid]            = seq_var[row0 * 32 + tid];
    else if (tid < 64)  sI[36 + tid - 32]  = seq_var[row1 * 32 + (tid - 32)];
    else if (tid < 67)  sI[32 + tid - 64]  = item_var[row0 * 3 + (tid - 64)];
    else if (tid < 70)  sI[68 + tid - 67]  = item_var[row1 * 3 + (tid - 67)];
    else if (tid == 70) sI[35]             = user_var[row0];
    else if (tid == 71) sI[71]             = user_var[row1];

    // ---- phase B: pack Wf2 B-fragments ONCE (batch-invariant) ----
    // W(n,k): n<100 & k<100 -> Wf2[n][k]; n<100 & k==100 -> bf2[n]; else 0.
    for (int idx = tid; idx < 13 * 7 * 32; idx += THREADS) {
        int nt  = idx / 224;
        int rem = idx - nt * 224;
        int ks  = rem >> 5, ln = rem & 31;
        int n   = nt * 8 + (ln >> 2);
        int k0  = ks * 16 + (ln & 3) * 2;
        float w0, w1, w2v, w3v;
        if (n < 100) {
            const float* wr = Wf2 + n * 100;
            w0  = (k0     < 100) ? wr[k0]     : ((k0     == 100) ? bf2[n] : 0.0f);
            w1  = (k0 + 1 < 100) ? wr[k0 + 1] : ((k0 + 1 == 100) ? bf2[n] : 0.0f);
            w2v = (k0 + 8 < 100) ? wr[k0 + 8] : ((k0 + 8 == 100) ? bf2[n] : 0.0f);
            w3v = (k0 + 9 < 100) ? wr[k0 + 9] : ((k0 + 9 == 100) ? bf2[n] : 0.0f);
        } else {
            w0 = w1 = w2v = w3v = 0.0f;
        }
        __half2 lo = __floats2half2_rn(w0, w1);
        __half2 hi = __floats2half2_rn(w2v, w3v);
        uint2 val;
        val.x = *reinterpret_cast<uint32_t*>(&lo);
        val.y = *reinterpret_cast<uint32_t*>(&hi);
        if (nt < 12) {
            *(uint2*)(smem + OFF_BFRAGP + (((nt >> 1) * 7 + ks) * 32 + ln) * 16
                               + (nt & 1) * 8) = val;
        } else {
            *(uint2*)(smem + OFF_F12 + (ks * 32 + ln) * 8) = val;
        }
    }

    const uint4* bfragP  = (const uint4*)(smem + OFF_BFRAGP);
    const uint2* bfrag12 = (const uint2*)(smem + OFF_F12);
    const int gid = lane >> 2;   // row group 0..7
    const int tig = lane & 3;    // k group 0..3

    // ==== per-batch-row loop ====
    for (int r = 0; r < 2; ++r) {
        const int ib = r * 36;   // index base in sI
        __syncthreads();

        // ---- phase 1: gather E^T for row r ----
        for (int idx = tid; idx < 2048; idx += THREADS) {
            int l = idx >> 6, d = idx & 63;
            sEt[d * 33 + l] = item_emb[(size_t)sI[ib + l] * 64 + d];
        }

        // ---- phase 2: A = E@Wa^T + b1, B = E@Wb^T (W1 staged) ----
        float* sW1c = (float*)(smem + OFF_W1);  // [100][64]
        for (int c = 0; c < 2; ++c) {
            __syncthreads();
            for (int idx = tid; idx < 6400; idx += THREADS) {
                int f = idx >> 6, jj = idx & 63;
                int half_ = jj >> 5, j = jj & 31;
                sW1c[idx] = W1[f * 128 + half_ * 64 + c * 32 + j];
            }
            __syncthreads();
            for (int idx = tid; idx < 3200; idx += THREADS) {
                int f = idx >> 5, l = idx & 31;
                float accA = 0.0f, accB = 0.0f;
                #pragma unroll
                for (int j = 0; j < 32; ++j) {
                    float e = sEt[(c * 32 + j) * 33 + l];
                    accA = fmaf(e, sW1c[f * 64 + j],      accA);
                    accB = fmaf(e, sW1c[f * 64 + 32 + j], accB);
                }
                if (c == 0) { sAf[idx] = accA;          sBf[idx] = accB; }
                else        { sAf[idx] += accA + b1[f]; sBf[idx] += accB; }
            }
        }
        __syncthreads();

        // ---- phase 3: pack half2 tables, transposed + pair-slotted ----
        for (int idx = tid; idx < 32 * 56; idx += THREADS) {
            int c = idx / 56, kk = idx - c * 56;
            __half2 va, vb;
            if (kk < 50) {
                va = __floats2half2_rn(sAf[(2 * kk) * 32 + c], sAf[(2 * kk + 1) * 32 + c]);
                vb = __floats2half2_rn(sBf[(2 * kk) * 32 + c], sBf[(2 * kk + 1) * 32 + c]);
            } else if (kk == 50) {
                va = __floats2half2_rn(1.0f, 0.0f);
                vb = __float2half2_rn(0.0f);
            } else {
                va = __float2half2_rn(0.0f);
                vb = __float2half2_rn(0.0f);
            }
            int s = pslot(kk);
            uA2[c * TSTR + s] = *reinterpret_cast<uint32_t*>(&va);
            uB2[c * TSTR + s] = *reinterpret_cast<uint32_t*>(&vb);
        }
        __syncthreads();

        // ---- mainloop: 8 m-tiles of 16 pairs per warp; no CTA syncs ----
        float xacc[26];
        #pragma unroll
        for (int j = 0; j < 26; ++j) xacc[j] = 0.0f;

        for (int mt = 0; mt < 8; ++mt) {
            const int p0 = wid * 128 + mt * 16 + gid;
            const int aI = p0 >> 5;
            const int cA = p0 & 31;
            const int cB = cA + 8;

            float acc[13][4];
            #pragma unroll
            for (int nt = 0; nt < 13; ++nt)
                #pragma unroll
                for (int e = 0; e < 4; ++e) acc[nt][e] = 0.0f;

            // prefetch ks=0 table fragments
            uint2 Bab = *(const uint2*)&uB2[aI * TSTR + tig * 2];
            uint2 Aa  = *(const uint2*)&uA2[cA * TSTR + tig * 2];
            uint2 Ab  = *(const uint2*)&uA2[cB * TSTR + tig * 2];

            #pragma unroll
            for (int ks = 0; ks < 7; ++ks) {
                uint32_t a0 = hbuild(Aa.x, Bab.x);
                uint32_t a1 = hbuild(Ab.x, Bab.x);
                uint32_t a2 = hbuild(Aa.y, Bab.y);
                uint32_t a3 = hbuild(Ab.y, Bab.y);
                if (ks < 6) {   // prefetch next ks (overlaps the MMA burst)
                    const int so = (ks + 1) * 8 + tig * 2;
                    Bab = *(const uint2*)&uB2[aI * TSTR + so];
                    Aa  = *(const uint2*)&uA2[cA * TSTR + so];
                    Ab  = *(const uint2*)&uA2[cB * TSTR + so];
                }
                #pragma unroll
                for (int ntp = 0; ntp < 6; ++ntp) {
                    uint4 bb = bfragP[(ntp * 7 + ks) * 32 + lane];
                    mma16816(acc[ntp * 2],     a0, a1, a2, a3, bb.x, bb.y);
                    mma16816(acc[ntp * 2 + 1], a0, a1, a2, a3, bb.z, bb.w);
                }
                uint2 b12 = bfrag12[ks * 32 + lane];
                mma16816(acc[12], a0, a1, a2, a3, b12.x, b12.y);
            }
            #pragma unroll
            for (int nt = 0; nt < 13; ++nt) {
                xacc[nt * 2]     += fmaxf(acc[nt][0], 0.0f) + fmaxf(acc[nt][2], 0.0f);
                xacc[nt * 2 + 1] += fmaxf(acc[nt][1], 0.0f) + fmaxf(acc[nt][3], 0.0f);
            }
        }

        // ---- reduction: shfl, then fixed-order over warps ----
        #pragma unroll
        for (int j = 0; j < 26; ++j) {
            float s = xacc[j];
            s += __shfl_down_sync(0xffffffffu, s, 16);
            s += __shfl_down_sync(0xffffffffu, s, 8);
            s += __shfl_down_sync(0xffffffffu, s, 4);
            xacc[j] = s;
        }
        float* sRedW = (float*)(smem + OFF_ET);  // [8][104], overlays dead E^T
        if (lane < 4) {
            #pragma unroll
            for (int nt = 0; nt < 13; ++nt) {
                int n0 = nt * 8 + lane * 2;
                sRedW[wid * 104 + n0]     = xacc[nt * 2];
                sRedW[wid * 104 + n0 + 1] = xacc[nt * 2 + 1];
            }
        }
        __syncthreads();
        if (tid < 100) {
            float s = 0.0f;
            #pragma unroll
            for (int w = 0; w < 8; ++w) s += sRedW[w * 104 + tid];
            sX[r * 164 + tid] = s;
        } else if (tid >= 128 && tid < 192) {
            int d = tid - 128;
            sX[r * 164 + 100 + d] = user_emb[(size_t)sI[ib + 35] * 64 + d];
        }
    }
    __syncthreads();

    // ---- out[row][t] = b2[item] + W2[item] . sX[r]  (one warp per output) ----
    if (wid < 6) {
        int r  = wid / 3, t = wid - r * 3;
        int it = sI[r * 36 + 32 + t];
        const float* w2p = W2 + (size_t)it * 164;
        const float* xp  = sX + r * 164;
        float s = 0.0f;
        for (int j = lane; j < 164; j += 32) s = fmaf(w2p[j], xp[j], s);
        #pragma unroll
        for (int off = 16; off; off >>= 1)
            s += __shfl_down_sync(0xffffffffu, s, off);
        if (lane == 0) out[(row0 + r) * 3 + t] = b2[it] + s;
    }
}

extern "C" void kernel_launch(void* const* d_in, const int* in_sizes, int n_in,
                              void* d_out, int out_size) {
    (void)in_sizes; (void)n_in; (void)out_size;
    cudaFuncSetAttribute(cosrec_kernel,
                         cudaFuncAttributeMaxDynamicSharedMemorySize, SMEM_TOTAL);
    cosrec_kernel<<<256, THREADS, SMEM_TOTAL>>>(
        (const int*)d_in[0],    // seq_var
        (const int*)d_in[1],    // user_var
        (const int*)d_in[2],    // item_var
        (const float*)d_in[3],  // item_emb
        (const float*)d_in[4],  // user_emb
        (const float*)d_in[5],  // W2
        (const float*)d_in[6],  // b2
        (const float*)d_in[7],  // W1
        (const float*)d_in[8],  // b1
        (const float*)d_in[9],  // Wf2
        (const float*)d_in[10], // bf2
        (float*)d_out);
}

// round 12
// speedup vs baseline: 1.7248x; 1.6528x over previous
#include <cuda_runtime.h>
#include <cuda_fp16.h>
#include <stdint.h>

// CosRec fused kernel — fp16 mma.sync (HMMA), round 12.
// vs round 11: phase 2 (A = E@Wa^T + b1, B = E@Wb^T) is now ALSO done with
// HMMA (k padded to 80; bias via E[:,64]=1, W1-row=b1), and the MMA output
// fragments are stored DIRECTLY into the half2 operand tables — deleting the
// fp32 sAf/sBf arrays, the E^T staging, and the scalar pack phase entirely.
// E and W1 are quantized to fp16 (fp32 accumulate). Mainloop unchanged.

#define THREADS 256
#define TSTR 56            // mainloop table row stride (words)
#define TE   40            // E-fragment table row stride (words)

// ---- shared memory byte offsets ----
#define OFF_SI     0       // 72 ints (two rows)                      288 B
#define OFF_SX     288     // 2 x 164 floats                         1312 B
#define OFF_BFRAGP 1664    // uint4 Wf2 bfrag pairs 6*7*32*16 =     21504 B
#define OFF_F12    23168   // uint2 Wf2 bfrag nt=12: 7*32*8 =        1792 B
#define OFF_A2     24960   // uint32 A-table [32][56] =              7168 B
#define OFF_B2     32128   // uint32 B-table [32][56] =              7168 B
#define OFF_W1F    39296   // uint2 W1 bfrags 2*13*5*32*8 =         33280 B
#define OFF_E2     72576   // uint32 E-table [32][40] =              5120 B
#define OFF_RED    77696   // fp32 sRedW [8][104] =                  3328 B
#define SMEM_TOTAL 81024

__device__ __forceinline__ void mma16816(float* d, uint32_t a0, uint32_t a1,
                                         uint32_t a2, uint32_t a3,
                                         uint32_t b0, uint32_t b1) {
    asm volatile(
        "mma.sync.aligned.m16n8k16.row.col.f32.f16.f16.f32 "
        "{%0,%1,%2,%3}, {%4,%5,%6,%7}, {%8,%9}, {%0,%1,%2,%3};"
        : "+f"(d[0]), "+f"(d[1]), "+f"(d[2]), "+f"(d[3])
        : "r"(a0), "r"(a1), "r"(a2), "r"(a3), "r"(b0), "r"(b1));
}

__device__ __forceinline__ uint32_t hbuild(uint32_t a, uint32_t b) {
    __half2 av = *reinterpret_cast<__half2*>(&a);
    __half2 bv = *reinterpret_cast<__half2*>(&b);
    __half2 r  = __hmax2(__hadd2(av, bv), __float2half2_rn(0.0f));
    return *reinterpret_cast<uint32_t*>(&r);
}
__device__ __forceinline__ uint32_t h2bits(__half2 v) {
    return *reinterpret_cast<uint32_t*>(&v);
}

// paired slot: (k2, k2+4) adjacent -> slot = blk + (k2&3)*2 + ((k2>>2)&1)
__device__ __forceinline__ int pslot(int kk) {
    return (kk & ~7) + ((kk & 3) << 1) + ((kk >> 2) & 1);
}

__global__ __launch_bounds__(THREADS, 2)
void cosrec_kernel(
    const int*   __restrict__ seq_var,   // [512*32]
    const int*   __restrict__ user_var,  // [512]
    const int*   __restrict__ item_var,  // [512*3]
    const float* __restrict__ item_emb,  // [100000*64]
    const float* __restrict__ user_emb,  // [100000*64]
    const float* __restrict__ W2,        // [100000*164]
    const float* __restrict__ b2,        // [100000]
    const float* __restrict__ W1,        // [100*128]
    const float* __restrict__ b1,        // [100]
    const float* __restrict__ Wf2,       // [100*100]
    const float* __restrict__ bf2,       // [100]
    float*       __restrict__ out)       // [512*3]
{
    extern __shared__ char smem[];
    int*      sI   = (int*)(smem + OFF_SI);
    float*    sX   = (float*)(smem + OFF_SX);     // [2][164]
    uint32_t* uA2  = (uint32_t*)(smem + OFF_A2);
    uint32_t* uB2  = (uint32_t*)(smem + OFF_B2);
    uint32_t* uE2  = (uint32_t*)(smem + OFF_E2);
    uint2*    bfW1 = (uint2*)(smem + OFF_W1F);

    const int row0 = blockIdx.x * 2;
    const int row1 = row0 + 1;
    const int tid  = threadIdx.x;
    const int wid  = tid >> 5;
    const int lane = tid & 31;

    // ---- phase 0: indices for both rows ----
    if (tid < 32)       sI[tid]            = seq_var[row0 * 32 + tid];
    else if (tid < 64)  sI[36 + tid - 32]  = seq_var[row1 * 32 + (tid - 32)];
    else if (tid < 67)  sI[32 + tid - 64]  = item_var[row0 * 3 + (tid - 64)];
    else if (tid < 70)  sI[68 + tid - 67]  = item_var[row1 * 3 + (tid - 67)];
    else if (tid == 70) sI[35]             = user_var[row0];
    else if (tid == 71) sI[71]             = user_var[row1];

    // ---- phase B1: pack Wf2 b-fragments ONCE (batch-invariant) ----
    for (int idx = tid; idx < 13 * 7 * 32; idx += THREADS) {
        int nt  = idx / 224;
        int rem = idx - nt * 224;
        int ks  = rem >> 5, ln = rem & 31;
        int n   = nt * 8 + (ln >> 2);
        int k0  = ks * 16 + (ln & 3) * 2;
        float w0, w1, w2v, w3v;
        if (n < 100) {
            const float* wr = Wf2 + n * 100;
            w0  = (k0     < 100) ? wr[k0]     : ((k0     == 100) ? bf2[n] : 0.0f);
            w1  = (k0 + 1 < 100) ? wr[k0 + 1] : ((k0 + 1 == 100) ? bf2[n] : 0.0f);
            w2v = (k0 + 8 < 100) ? wr[k0 + 8] : ((k0 + 8 == 100) ? bf2[n] : 0.0f);
            w3v = (k0 + 9 < 100) ? wr[k0 + 9] : ((k0 + 9 == 100) ? bf2[n] : 0.0f);
        } else {
            w0 = w1 = w2v = w3v = 0.0f;
        }
        uint2 val;
        val.x = h2bits(__floats2half2_rn(w0, w1));
        val.y = h2bits(__floats2half2_rn(w2v, w3v));
        if (nt < 12) {
            *(uint2*)(smem + OFF_BFRAGP + (((nt >> 1) * 7 + ks) * 32 + ln) * 16
                               + (nt & 1) * 8) = val;
        } else {
            *(uint2*)(smem + OFF_F12 + (ks * 32 + ln) * 8) = val;
        }
    }

    // ---- phase B2: pack W1 b-fragments ONCE (part 0 = Wa + b1 col, 1 = Wb) ----
    // Wpart(f,k): f<100 & k<64 -> W1[f*128 + part*64 + k];
    //             part==0 & k==64 -> b1[f]; else 0.   (k padded to 80)
    for (int idx = tid; idx < 2 * 13 * 5 * 32; idx += THREADS) {
        int p   = idx / 2080;
        int rem = idx - p * 2080;
        int nt  = rem / 160;
        int r2  = rem - nt * 160;
        int ks  = r2 >> 5, ln = r2 & 31;
        int f   = nt * 8 + (ln >> 2);
        int k0  = ks * 16 + (ln & 3) * 2;
        float w[4] = {0.0f, 0.0f, 0.0f, 0.0f};
        if (f < 100) {
            const float* wr = W1 + f * 128 + p * 64;
            int kk4[4] = {k0, k0 + 1, k0 + 8, k0 + 9};
            #pragma unroll
            for (int q = 0; q < 4; ++q) {
                int k = kk4[q];
                if (k < 64)                    w[q] = wr[k];
                else if (p == 0 && k == 64)    w[q] = b1[f];
            }
        }
        uint2 val;
        val.x = h2bits(__floats2half2_rn(w[0], w[1]));
        val.y = h2bits(__floats2half2_rn(w[2], w[3]));
        bfW1[((p * 13 + nt) * 5 + ks) * 32 + ln] = val;
    }

    const uint4* bfragP  = (const uint4*)(smem + OFF_BFRAGP);
    const uint2* bfrag12 = (const uint2*)(smem + OFF_F12);
    const int gid = lane >> 2;   // row group 0..7
    const int tig = lane & 3;    // k group 0..3

    // ==== per-batch-row loop ====
    for (int r = 0; r < 2; ++r) {
        const int ib = r * 36;
        __syncthreads();   // prev row mainloop done; sE2/tables free; packs done

        // ---- phase 1: gather E as fp16 fragment table [l][pslot(d2)] ----
        // d2<32: (emb[2d2], emb[2d2+1]); d2==32: bias col (1,0); else 0.
        for (int idx = tid; idx < 32 * 40; idx += THREADS) {
            int l = idx / 40, d2 = idx - l * 40;
            __half2 v;
            if (d2 < 32) {
                const float* ep = item_emb + (size_t)sI[ib + l] * 64 + 2 * d2;
                v = __floats2half2_rn(ep[0], ep[1]);
            } else if (d2 == 32) {
                v = __floats2half2_rn(1.0f, 0.0f);
            } else {
                v = __float2half2_rn(0.0f);
            }
            uE2[l * TE + pslot(d2)] = h2bits(v);
        }
        // ---- init table slots kk=50..55 (bias col for mainloop + zero pad) ----
        for (int idx = tid; idx < 32 * 6; idx += THREADS) {
            int c = idx / 6, j = idx - c * 6;
            int s = pslot(50 + j);
            uA2[c * TSTR + s] = (j == 0) ? 0x00003C00u : 0u;  // (1.0h, 0)
            uB2[c * TSTR + s] = 0u;
        }
        __syncthreads();

        // ---- phase 2: A/B via HMMA, fragments stored straight to tables ----
        // combos: part p (A/B) x mt (2) x nt (13) = 52, strided over 8 warps.
        for (int cb = wid; cb < 52; cb += 8) {
            const int mt = cb & 1;
            const int pn = cb >> 1;
            const int p  = pn / 13;
            const int nt = pn - p * 13;
            const int c0 = mt * 16 + gid;

            float acc[4] = {0.0f, 0.0f, 0.0f, 0.0f};
            #pragma unroll
            for (int ks = 0; ks < 5; ++ks) {
                const int so = ks * 8 + tig * 2;
                uint2 Aa = *(const uint2*)&uE2[c0 * TE + so];
                uint2 Ab = *(const uint2*)&uE2[(c0 + 8) * TE + so];
                uint2 bb = bfW1[((p * 13 + nt) * 5 + ks) * 32 + lane];
                mma16816(acc, Aa.x, Ab.x, Aa.y, Ab.y, bb.x, bb.y);
            }
            const int kk = nt * 4 + tig;    // table k2 index (= f pair /2)
            if (kk < 50) {
                uint32_t* tbl = p ? uB2 : uA2;
                const int s = pslot(kk);
                tbl[c0 * TSTR + s]       = h2bits(__floats2half2_rn(acc[0], acc[1]));
                tbl[(c0 + 8) * TSTR + s] = h2bits(__floats2half2_rn(acc[2], acc[3]));
            }
        }
        __syncthreads();

        // ---- mainloop: 8 m-tiles of 16 pairs per warp; no CTA syncs ----
        float xacc[26];
        #pragma unroll
        for (int j = 0; j < 26; ++j) xacc[j] = 0.0f;

        for (int mt = 0; mt < 8; ++mt) {
            const int p0 = wid * 128 + mt * 16 + gid;
            const int aI = p0 >> 5;
            const int cA = p0 & 31;
            const int cB = cA + 8;

            float acc[13][4];
            #pragma unroll
            for (int nt = 0; nt < 13; ++nt)
                #pragma unroll
                for (int e = 0; e < 4; ++e) acc[nt][e] = 0.0f;

            uint2 Bab = *(const uint2*)&uB2[aI * TSTR + tig * 2];
            uint2 Aa  = *(const uint2*)&uA2[cA * TSTR + tig * 2];
            uint2 Ab  = *(const uint2*)&uA2[cB * TSTR + tig * 2];

            #pragma unroll
            for (int ks = 0; ks < 7; ++ks) {
                uint32_t a0 = hbuild(Aa.x, Bab.x);
                uint32_t a1 = hbuild(Ab.x, Bab.x);
                uint32_t a2 = hbuild(Aa.y, Bab.y);
                uint32_t a3 = hbuild(Ab.y, Bab.y);
                if (ks < 6) {
                    const int so = (ks + 1) * 8 + tig * 2;
                    Bab = *(const uint2*)&uB2[aI * TSTR + so];
                    Aa  = *(const uint2*)&uA2[cA * TSTR + so];
                    Ab  = *(const uint2*)&uA2[cB * TSTR + so];
                }
                #pragma unroll
                for (int ntp = 0; ntp < 6; ++ntp) {
                    uint4 bb = bfragP[(ntp * 7 + ks) * 32 + lane];
                    mma16816(acc[ntp * 2],     a0, a1, a2, a3, bb.x, bb.y);
                    mma16816(acc[ntp * 2 + 1], a0, a1, a2, a3, bb.z, bb.w);
                }
                uint2 b12 = bfrag12[ks * 32 + lane];
                mma16816(acc[12], a0, a1, a2, a3, b12.x, b12.y);
            }
            #pragma unroll
            for (int nt = 0; nt < 13; ++nt) {
                xacc[nt * 2]     += fmaxf(acc[nt][0], 0.0f) + fmaxf(acc[nt][2], 0.0f);
                xacc[nt * 2 + 1] += fmaxf(acc[nt][1], 0.0f) + fmaxf(acc[nt][3], 0.0f);
            }
        }

        // ---- reduction: shfl, then fixed-order over warps ----
        #pragma unroll
        for (int j = 0; j < 26; ++j) {
            float s = xacc[j];
            s += __shfl_down_sync(0xffffffffu, s, 16);
            s += __shfl_down_sync(0xffffffffu, s, 8);
            s += __shfl_down_sync(0xffffffffu, s, 4);
            xacc[j] = s;
        }
        float* sRedW = (float*)(smem + OFF_RED);  // [8][104]
        if (lane < 4) {
            #pragma unroll
            for (int nt = 0; nt < 13; ++nt) {
                int n0 = nt * 8 + lane * 2;
                sRedW[wid * 104 + n0]     = xacc[nt * 2];
                sRedW[wid * 104 + n0 + 1] = xacc[nt * 2 + 1];
            }
        }
        __syncthreads();
        if (tid < 100) {
            float s = 0.0f;
            #pragma unroll
            for (int w = 0; w < 8; ++w) s += sRedW[w * 104 + tid];
            sX[r * 164 + tid] = s;
        } else if (tid >= 128 && tid < 192) {
            int d = tid - 128;
            sX[r * 164 + 100 + d] = user_emb[(size_t)sI[ib + 35] * 64 + d];
        }
    }
    __syncthreads();

    // ---- out[row][t] = b2[item] + W2[item] . sX[r]  (one warp per output) ----
    if (wid < 6) {
        int r  = wid / 3, t = wid - r * 3;
        int it = sI[r * 36 + 32 + t];
        const float* w2p = W2 + (size_t)it * 164;
        const float* xp  = sX + r * 164;
        float s = 0.0f;
        for (int j = lane; j < 164; j += 32) s = fmaf(w2p[j], xp[j], s);
        #pragma unroll
        for (int off = 16; off; off >>= 1)
            s += __shfl_down_sync(0xffffffffu, s, off);
        if (lane == 0) out[(row0 + r) * 3 + t] = b2[it] + s;
    }
}

extern "C" void kernel_launch(void* const* d_in, const int* in_sizes, int n_in,
                              void* d_out, int out_size) {
    (void)in_sizes; (void)n_in; (void)out_size;
    cudaFuncSetAttribute(cosrec_kernel,
                         cudaFuncAttributeMaxDynamicSharedMemorySize, SMEM_TOTAL);
    cosrec_kernel<<<256, THREADS, SMEM_TOTAL>>>(
        (const int*)d_in[0],    // seq_var
        (const int*)d_in[1],    // user_var
        (const int*)d_in[2],    // item_var
        (const float*)d_in[3],  // item_emb
        (const float*)d_in[4],  // user_emb
        (const float*)d_in[5],  // W2
        (const float*)d_in[6],  // b2
        (const float*)d_in[7],  // W1
        (const float*)d_in[8],  // b1
        (const float*)d_in[9],  // Wf2
        (const float*)d_in[10], // bf2
        (float*)d_out);
}